// round 8
// baseline (speedup 1.0000x reference)
#include <cuda_runtime.h>
#include <cuda_bf16.h>
#include <cstdint>

// Problem constants (static shapes from reference)
#define NUM_EXPERTS   64
#define DIM           2048
#define HIDDEN_DIM    1024
#define TOKENS_PER_E  256
#define TOTAL_TOKENS  (NUM_EXPERTS * TOKENS_PER_E)   // 16384

// Tiling
#define BM 128
#define BN 64
#define BK 32
#define XS_STRIDE (BK + 4)   // 36 floats = 144B (16B-aligned rows, conflict-free frags)
#define WS_STRIDE (BN + 8)   // 72 floats = 288B (16B-aligned rows, conflict-free frags)

// Scratch for intermediate h = silu(x@w1) * (x@w3): 16384 x 1024 fp32 = 64 MB
__device__ float g_h[(size_t)TOTAL_TOKENS * HIDDEN_DIM];

// ---- helpers ---------------------------------------------------------------

__device__ __forceinline__ float tf32_rna(float f) {
    // Round-to-nearest tf32. Avoids the truncation bias of raw mma tf32 operand use.
    asm("cvt.rna.tf32.f32 %0, %0;" : "+f"(f));
    return f;
}

__device__ __forceinline__ void mma_tf32(float c[4],
                                         const uint32_t a[4],
                                         uint32_t b0, uint32_t b1) {
    asm volatile(
        "mma.sync.aligned.m16n8k8.row.col.f32.tf32.tf32.f32 "
        "{%0,%1,%2,%3}, {%4,%5,%6,%7}, {%8,%9}, {%0,%1,%2,%3};"
        : "+f"(c[0]), "+f"(c[1]), "+f"(c[2]), "+f"(c[3])
        : "r"(a[0]), "r"(a[1]), "r"(a[2]), "r"(a[3]), "r"(b0), "r"(b1));
}

__device__ __forceinline__ float swiglu(float g, float u) {
    // silu(g) * u
    return (g / (1.0f + __expf(-g))) * u;
}

// ---- Kernel A: h = silu(x @ w1[e]) * (x @ w3[e]) ---------------------------
// Grid: (HIDDEN_DIM/BN = 16, TOKENS_PER_E/BM = 2, NUM_EXPERTS = 64)

__global__ __launch_bounds__(256, 2)
void moe_up_kernel(const float* __restrict__ x,
                   const float* __restrict__ w1,
                   const float* __restrict__ w3) {
    __shared__ float Xs[BM * XS_STRIDE];
    __shared__ float W1s[BK * WS_STRIDE];
    __shared__ float W3s[BK * WS_STRIDE];

    const int e    = blockIdx.z;
    const int mblk = blockIdx.y;
    const int nblk = blockIdx.x;
    const int tid  = threadIdx.x;
    const int lane = tid & 31;
    const int warp = tid >> 5;
    const int wm   = warp >> 1;   // 0..3 (M)
    const int wn   = warp & 1;    // 0..1 (N)

    const int tok_base = e * TOKENS_PER_E + mblk * BM;
    const float* xg  = x  + (size_t)tok_base * DIM;
    const float* w1g = w1 + (size_t)e * DIM * HIDDEN_DIM + nblk * BN;
    const float* w3g = w3 + (size_t)e * DIM * HIDDEN_DIM + nblk * BN;

    float acc1[2][4][4];
    float acc3[2][4][4];
#pragma unroll
    for (int mt = 0; mt < 2; mt++)
#pragma unroll
        for (int nt = 0; nt < 4; nt++)
#pragma unroll
            for (int i = 0; i < 4; i++) { acc1[mt][nt][i] = 0.0f; acc3[mt][nt][i] = 0.0f; }

    // Global-load coordinates
    const int xr  = tid >> 3;          // 0..31 (rows per pass)
    const int xc4 = (tid & 7) * 4;     // 0..28
    const int wr  = tid >> 4;          // 0..15
    const int wc4 = (tid & 15) * 4;    // 0..60

#pragma unroll 1
    for (int k0 = 0; k0 < DIM; k0 += BK) {
        // ---- load X tile [BM x BK] ----
#pragma unroll
        for (int p = 0; p < 4; p++) {
            const int row = xr + p * 32;
            float4 v = *reinterpret_cast<const float4*>(xg + (size_t)row * DIM + k0 + xc4);
            v.x = tf32_rna(v.x); v.y = tf32_rna(v.y); v.z = tf32_rna(v.z); v.w = tf32_rna(v.w);
            *reinterpret_cast<float4*>(&Xs[row * XS_STRIDE + xc4]) = v;
        }
        // ---- load W1/W3 tiles [BK x BN] ----
#pragma unroll
        for (int p = 0; p < 2; p++) {
            const int row = wr + p * 16;
            float4 v1 = *reinterpret_cast<const float4*>(w1g + (size_t)(k0 + row) * HIDDEN_DIM + wc4);
            float4 v3 = *reinterpret_cast<const float4*>(w3g + (size_t)(k0 + row) * HIDDEN_DIM + wc4);
            v1.x = tf32_rna(v1.x); v1.y = tf32_rna(v1.y); v1.z = tf32_rna(v1.z); v1.w = tf32_rna(v1.w);
            v3.x = tf32_rna(v3.x); v3.y = tf32_rna(v3.y); v3.z = tf32_rna(v3.z); v3.w = tf32_rna(v3.w);
            *reinterpret_cast<float4*>(&W1s[row * WS_STRIDE + wc4]) = v1;
            *reinterpret_cast<float4*>(&W3s[row * WS_STRIDE + wc4]) = v3;
        }
        __syncthreads();

        // ---- compute: 4 k-steps of m16n8k8 ----
#pragma unroll
        for (int ks = 0; ks < BK; ks += 8) {
            uint32_t a[2][4];
            const int ar = wm * 32 + (lane >> 2);
            const int ac = ks + (lane & 3);
#pragma unroll
            for (int mt = 0; mt < 2; mt++) {
                const int r = ar + mt * 16;
                a[mt][0] = __float_as_uint(Xs[r       * XS_STRIDE + ac]);
                a[mt][1] = __float_as_uint(Xs[(r + 8) * XS_STRIDE + ac]);
                a[mt][2] = __float_as_uint(Xs[r       * XS_STRIDE + ac + 4]);
                a[mt][3] = __float_as_uint(Xs[(r + 8) * XS_STRIDE + ac + 4]);
            }
            const int br = ks + (lane & 3);
#pragma unroll
            for (int nt = 0; nt < 4; nt++) {
                const int bc = wn * 32 + nt * 8 + (lane >> 2);
                const uint32_t b1_0 = __float_as_uint(W1s[br       * WS_STRIDE + bc]);
                const uint32_t b1_1 = __float_as_uint(W1s[(br + 4) * WS_STRIDE + bc]);
                const uint32_t b3_0 = __float_as_uint(W3s[br       * WS_STRIDE + bc]);
                const uint32_t b3_1 = __float_as_uint(W3s[(br + 4) * WS_STRIDE + bc]);
#pragma unroll
                for (int mt = 0; mt < 2; mt++) {
                    mma_tf32(acc1[mt][nt], a[mt], b1_0, b1_1);
                    mma_tf32(acc3[mt][nt], a[mt], b3_0, b3_1);
                }
            }
        }
        __syncthreads();
    }

    // ---- epilogue: swiglu, store h ----
    const int row_base = wm * 32 + (lane >> 2);
    const int col_base = nblk * BN + wn * 32 + (lane & 3) * 2;
#pragma unroll
    for (int mt = 0; mt < 2; mt++) {
        const int r0 = tok_base + row_base + mt * 16;
#pragma unroll
        for (int nt = 0; nt < 4; nt++) {
            const int c = col_base + nt * 8;
            float2 lo, hi;
            lo.x = swiglu(acc1[mt][nt][0], acc3[mt][nt][0]);
            lo.y = swiglu(acc1[mt][nt][1], acc3[mt][nt][1]);
            hi.x = swiglu(acc1[mt][nt][2], acc3[mt][nt][2]);
            hi.y = swiglu(acc1[mt][nt][3], acc3[mt][nt][3]);
            *reinterpret_cast<float2*>(&g_h[(size_t)r0 * HIDDEN_DIM + c])       = lo;
            *reinterpret_cast<float2*>(&g_h[(size_t)(r0 + 8) * HIDDEN_DIM + c]) = hi;
        }
    }
}

// ---- Kernel B: out = h @ w2[e] ---------------------------------------------
// Grid: (DIM/BN = 32, TOKENS_PER_E/BM = 2, NUM_EXPERTS = 64)

__global__ __launch_bounds__(256, 2)
void moe_down_kernel(const float* __restrict__ w2,
                     float* __restrict__ out) {
    __shared__ float Hs[BM * XS_STRIDE];
    __shared__ float Ws[BK * WS_STRIDE];

    const int e    = blockIdx.z;
    const int mblk = blockIdx.y;
    const int nblk = blockIdx.x;
    const int tid  = threadIdx.x;
    const int lane = tid & 31;
    const int warp = tid >> 5;
    const int wm   = warp >> 1;
    const int wn   = warp & 1;

    const int tok_base = e * TOKENS_PER_E + mblk * BM;
    const float* hg  = g_h + (size_t)tok_base * HIDDEN_DIM;
    const float* w2g = w2  + (size_t)e * HIDDEN_DIM * DIM + nblk * BN;

    float acc[2][4][4];
#pragma unroll
    for (int mt = 0; mt < 2; mt++)
#pragma unroll
        for (int nt = 0; nt < 4; nt++)
#pragma unroll
            for (int i = 0; i < 4; i++) acc[mt][nt][i] = 0.0f;

    const int xr  = tid >> 3;
    const int xc4 = (tid & 7) * 4;
    const int wr  = tid >> 4;
    const int wc4 = (tid & 15) * 4;

#pragma unroll 1
    for (int k0 = 0; k0 < HIDDEN_DIM; k0 += BK) {
#pragma unroll
        for (int p = 0; p < 4; p++) {
            const int row = xr + p * 32;
            float4 v = *reinterpret_cast<const float4*>(hg + (size_t)row * HIDDEN_DIM + k0 + xc4);
            v.x = tf32_rna(v.x); v.y = tf32_rna(v.y); v.z = tf32_rna(v.z); v.w = tf32_rna(v.w);
            *reinterpret_cast<float4*>(&Hs[row * XS_STRIDE + xc4]) = v;
        }
#pragma unroll
        for (int p = 0; p < 2; p++) {
            const int row = wr + p * 16;
            float4 v = *reinterpret_cast<const float4*>(w2g + (size_t)(k0 + row) * DIM + wc4);
            v.x = tf32_rna(v.x); v.y = tf32_rna(v.y); v.z = tf32_rna(v.z); v.w = tf32_rna(v.w);
            *reinterpret_cast<float4*>(&Ws[row * WS_STRIDE + wc4]) = v;
        }
        __syncthreads();

#pragma unroll
        for (int ks = 0; ks < BK; ks += 8) {
            uint32_t a[2][4];
            const int ar = wm * 32 + (lane >> 2);
            const int ac = ks + (lane & 3);
#pragma unroll
            for (int mt = 0; mt < 2; mt++) {
                const int r = ar + mt * 16;
                a[mt][0] = __float_as_uint(Hs[r       * XS_STRIDE + ac]);
                a[mt][1] = __float_as_uint(Hs[(r + 8) * XS_STRIDE + ac]);
                a[mt][2] = __float_as_uint(Hs[r       * XS_STRIDE + ac + 4]);
                a[mt][3] = __float_as_uint(Hs[(r + 8) * XS_STRIDE + ac + 4]);
            }
            const int br = ks + (lane & 3);
#pragma unroll
            for (int nt = 0; nt < 4; nt++) {
                const int bc = wn * 32 + nt * 8 + (lane >> 2);
                const uint32_t b0 = __float_as_uint(Ws[br       * WS_STRIDE + bc]);
                const uint32_t b1 = __float_as_uint(Ws[(br + 4) * WS_STRIDE + bc]);
#pragma unroll
                for (int mt = 0; mt < 2; mt++) {
                    mma_tf32(acc[mt][nt], a[mt], b0, b1);
                }
            }
        }
        __syncthreads();
    }

    const int row_base = wm * 32 + (lane >> 2);
    const int col_base = nblk * BN + wn * 32 + (lane & 3) * 2;
#pragma unroll
    for (int mt = 0; mt < 2; mt++) {
        const int r0 = tok_base + row_base + mt * 16;
#pragma unroll
        for (int nt = 0; nt < 4; nt++) {
            const int c = col_base + nt * 8;
            float2 lo = make_float2(acc[mt][nt][0], acc[mt][nt][1]);
            float2 hi = make_float2(acc[mt][nt][2], acc[mt][nt][3]);
            *reinterpret_cast<float2*>(&out[(size_t)r0 * DIM + c])       = lo;
            *reinterpret_cast<float2*>(&out[(size_t)(r0 + 8) * DIM + c]) = hi;
        }
    }
}

// ---- launch ----------------------------------------------------------------

extern "C" void kernel_launch(void* const* d_in, const int* in_sizes, int n_in,
                              void* d_out, int out_size) {
    const float* x  = (const float*)d_in[0];
    const float* w1 = (const float*)d_in[1];
    const float* w2 = (const float*)d_in[2];
    const float* w3 = (const float*)d_in[3];
    // d_in[4] = num_local_tokens_per_expert: statically 256 each, unused.
    float* out = (float*)d_out;

    dim3 blk(256);
    moe_up_kernel<<<dim3(HIDDEN_DIM / BN, TOKENS_PER_E / BM, NUM_EXPERTS), blk>>>(x, w1, w3);
    moe_down_kernel<<<dim3(DIM / BN, TOKENS_PER_E / BM, NUM_EXPERTS), blk>>>(w2, out);
}

// round 9
// speedup vs baseline: 1.0836x; 1.0836x over previous
#include <cuda_runtime.h>
#include <cuda_bf16.h>
#include <cstdint>

// Problem constants (static shapes from reference)
#define NUM_EXPERTS   64
#define DIM           2048
#define HIDDEN_DIM    1024
#define TOKENS_PER_E  256
#define TOTAL_TOKENS  (NUM_EXPERTS * TOKENS_PER_E)   // 16384

// Tiling
#define BM 128
#define BN 64
#define BK 32
#define XS_STRIDE (BK + 4)   // 36 floats (16B-aligned rows, conflict-free frags)
#define WS_STRIDE (BN + 8)   // 72 floats (16B-aligned rows, conflict-free frags)

#define X_BUF (BM * XS_STRIDE)   // 4608 floats
#define W_BUF (BK * WS_STRIDE)   // 2304 floats

// Smem (dynamic), double-buffered:
//   up:   X[2]*4608 + W1[2]*2304 + W3[2]*2304 = 18432 floats = 73728 B
//   down: H[2]*4608 + W2[2]*2304              = 13824 floats = 55296 B
#define SMEM_UP_BYTES   (2 * (X_BUF + 2 * W_BUF) * 4)
#define SMEM_DOWN_BYTES (2 * (X_BUF + W_BUF) * 4)

// Scratch for intermediate h: 16384 x 1024 fp32 = 64 MB
__device__ float g_h[(size_t)TOTAL_TOKENS * HIDDEN_DIM];

// ---- helpers ---------------------------------------------------------------

__device__ __forceinline__ float tf32_rna(float f) {
    asm("cvt.rna.tf32.f32 %0, %0;" : "+f"(f));
    return f;
}

__device__ __forceinline__ void mma_tf32(float c[4],
                                         const uint32_t a[4],
                                         uint32_t b0, uint32_t b1) {
    asm volatile(
        "mma.sync.aligned.m16n8k8.row.col.f32.tf32.tf32.f32 "
        "{%0,%1,%2,%3}, {%4,%5,%6,%7}, {%8,%9}, {%0,%1,%2,%3};"
        : "+f"(c[0]), "+f"(c[1]), "+f"(c[2]), "+f"(c[3])
        : "r"(a[0]), "r"(a[1]), "r"(a[2]), "r"(a[3]), "r"(b0), "r"(b1));
}

__device__ __forceinline__ float swiglu(float g, float u) {
    return (g / (1.0f + __expf(-g))) * u;
}

// Global-load / smem-store staging helpers ------------------------------------

__device__ __forceinline__ void ldg_x4(const float* __restrict__ base, int ld,
                                       int k0, int xr, int xc4, float4 v[4]) {
#pragma unroll
    for (int p = 0; p < 4; p++)
        v[p] = *reinterpret_cast<const float4*>(base + (size_t)(xr + p * 32) * ld + k0 + xc4);
}

__device__ __forceinline__ void sts_x4(float* __restrict__ Xb, int xr, int xc4,
                                       float4 v[4]) {
#pragma unroll
    for (int p = 0; p < 4; p++) {
        float4 t = v[p];
        t.x = tf32_rna(t.x); t.y = tf32_rna(t.y); t.z = tf32_rna(t.z); t.w = tf32_rna(t.w);
        *reinterpret_cast<float4*>(&Xb[(xr + p * 32) * XS_STRIDE + xc4]) = t;
    }
}

__device__ __forceinline__ void ldg_w2(const float* __restrict__ base, int ld,
                                       int k0, int wr, int wc4, float4 v[2]) {
#pragma unroll
    for (int p = 0; p < 2; p++)
        v[p] = *reinterpret_cast<const float4*>(base + (size_t)(k0 + wr + p * 16) * ld + wc4);
}

__device__ __forceinline__ void sts_w2(float* __restrict__ Wb, int wr, int wc4,
                                       float4 v[2]) {
#pragma unroll
    for (int p = 0; p < 2; p++) {
        float4 t = v[p];
        t.x = tf32_rna(t.x); t.y = tf32_rna(t.y); t.z = tf32_rna(t.z); t.w = tf32_rna(t.w);
        *reinterpret_cast<float4*>(&Wb[(wr + p * 16) * WS_STRIDE + wc4]) = t;
    }
}

// ---- Kernel A: h = silu(x @ w1[e]) * (x @ w3[e]) ---------------------------
// Grid: (HIDDEN_DIM/BN = 16, TOKENS_PER_E/BM = 2, NUM_EXPERTS = 64)

__global__ __launch_bounds__(256, 2)
void moe_up_kernel(const float* __restrict__ x,
                   const float* __restrict__ w1,
                   const float* __restrict__ w3) {
    extern __shared__ float sm[];
    float* Xs  = sm;                       // [2][X_BUF]
    float* W1s = sm + 2 * X_BUF;           // [2][W_BUF]
    float* W3s = sm + 2 * X_BUF + 2 * W_BUF;

    const int e    = blockIdx.z;
    const int mblk = blockIdx.y;
    const int nblk = blockIdx.x;
    const int tid  = threadIdx.x;
    const int lane = tid & 31;
    const int warp = tid >> 5;
    const int wm   = warp >> 1;   // 0..3 (M)
    const int wn   = warp & 1;    // 0..1 (N)

    const int tok_base = e * TOKENS_PER_E + mblk * BM;
    const float* xg  = x  + (size_t)tok_base * DIM;
    const float* w1g = w1 + (size_t)e * DIM * HIDDEN_DIM + nblk * BN;
    const float* w3g = w3 + (size_t)e * DIM * HIDDEN_DIM + nblk * BN;

    float acc1[2][4][4];
    float acc3[2][4][4];
#pragma unroll
    for (int mt = 0; mt < 2; mt++)
#pragma unroll
        for (int nt = 0; nt < 4; nt++)
#pragma unroll
            for (int i = 0; i < 4; i++) { acc1[mt][nt][i] = 0.0f; acc3[mt][nt][i] = 0.0f; }

    const int xr  = tid >> 3;
    const int xc4 = (tid & 7) * 4;
    const int wr  = tid >> 4;
    const int wc4 = (tid & 15) * 4;

    // Prologue: stage tile k0=0 into buffer 0
    {
        float4 px[4], p1[2], p3[2];
        ldg_x4(xg, DIM, 0, xr, xc4, px);
        ldg_w2(w1g, HIDDEN_DIM, 0, wr, wc4, p1);
        ldg_w2(w3g, HIDDEN_DIM, 0, wr, wc4, p3);
        sts_x4(Xs, xr, xc4, px);
        sts_w2(W1s, wr, wc4, p1);
        sts_w2(W3s, wr, wc4, p3);
    }
    __syncthreads();

    int cur = 0;
#pragma unroll 1
    for (int k0 = 0; k0 < DIM; k0 += BK) {
        const bool has_next = (k0 + BK) < DIM;

        // ---- prefetch next tile into registers (latency overlapped by compute)
        float4 px[4], p1[2], p3[2];
        if (has_next) {
            ldg_x4(xg, DIM, k0 + BK, xr, xc4, px);
            ldg_w2(w1g, HIDDEN_DIM, k0 + BK, wr, wc4, p1);
            ldg_w2(w3g, HIDDEN_DIM, k0 + BK, wr, wc4, p3);
        }

        const float* Xb  = Xs  + cur * X_BUF;
        const float* W1b = W1s + cur * W_BUF;
        const float* W3b = W3s + cur * W_BUF;

        // ---- compute current buffer: 4 k-steps of m16n8k8 ----
#pragma unroll
        for (int ks = 0; ks < BK; ks += 8) {
            uint32_t a[2][4];
            const int ar = wm * 32 + (lane >> 2);
            const int ac = ks + (lane & 3);
#pragma unroll
            for (int mt = 0; mt < 2; mt++) {
                const int r = ar + mt * 16;
                a[mt][0] = __float_as_uint(Xb[r       * XS_STRIDE + ac]);
                a[mt][1] = __float_as_uint(Xb[(r + 8) * XS_STRIDE + ac]);
                a[mt][2] = __float_as_uint(Xb[r       * XS_STRIDE + ac + 4]);
                a[mt][3] = __float_as_uint(Xb[(r + 8) * XS_STRIDE + ac + 4]);
            }
            const int br = ks + (lane & 3);
#pragma unroll
            for (int nt = 0; nt < 4; nt++) {
                const int bc = wn * 32 + nt * 8 + (lane >> 2);
                const uint32_t b1_0 = __float_as_uint(W1b[br       * WS_STRIDE + bc]);
                const uint32_t b1_1 = __float_as_uint(W1b[(br + 4) * WS_STRIDE + bc]);
                const uint32_t b3_0 = __float_as_uint(W3b[br       * WS_STRIDE + bc]);
                const uint32_t b3_1 = __float_as_uint(W3b[(br + 4) * WS_STRIDE + bc]);
#pragma unroll
                for (int mt = 0; mt < 2; mt++) {
                    mma_tf32(acc1[mt][nt], a[mt], b1_0, b1_1);
                    mma_tf32(acc3[mt][nt], a[mt], b3_0, b3_1);
                }
            }
        }

        // ---- stage prefetched tile into the other buffer ----
        if (has_next) {
            const int nxt = cur ^ 1;
            sts_x4(Xs  + nxt * X_BUF, xr, xc4, px);
            sts_w2(W1s + nxt * W_BUF, wr, wc4, p1);
            sts_w2(W3s + nxt * W_BUF, wr, wc4, p3);
        }
        __syncthreads();
        cur ^= 1;
    }

    // ---- epilogue: swiglu, store h ----
    const int row_base = wm * 32 + (lane >> 2);
    const int col_base = nblk * BN + wn * 32 + (lane & 3) * 2;
#pragma unroll
    for (int mt = 0; mt < 2; mt++) {
        const int r0 = tok_base + row_base + mt * 16;
#pragma unroll
        for (int nt = 0; nt < 4; nt++) {
            const int c = col_base + nt * 8;
            float2 lo, hi;
            lo.x = swiglu(acc1[mt][nt][0], acc3[mt][nt][0]);
            lo.y = swiglu(acc1[mt][nt][1], acc3[mt][nt][1]);
            hi.x = swiglu(acc1[mt][nt][2], acc3[mt][nt][2]);
            hi.y = swiglu(acc1[mt][nt][3], acc3[mt][nt][3]);
            *reinterpret_cast<float2*>(&g_h[(size_t)r0 * HIDDEN_DIM + c])       = lo;
            *reinterpret_cast<float2*>(&g_h[(size_t)(r0 + 8) * HIDDEN_DIM + c]) = hi;
        }
    }
}

// ---- Kernel B: out = h @ w2[e] ---------------------------------------------
// Grid: (DIM/BN = 32, TOKENS_PER_E/BM = 2, NUM_EXPERTS = 64)

__global__ __launch_bounds__(256, 2)
void moe_down_kernel(const float* __restrict__ w2,
                     float* __restrict__ out) {
    extern __shared__ float sm[];
    float* Hs = sm;              // [2][X_BUF]
    float* Ws = sm + 2 * X_BUF;  // [2][W_BUF]

    const int e    = blockIdx.z;
    const int mblk = blockIdx.y;
    const int nblk = blockIdx.x;
    const int tid  = threadIdx.x;
    const int lane = tid & 31;
    const int warp = tid >> 5;
    const int wm   = warp >> 1;
    const int wn   = warp & 1;

    const int tok_base = e * TOKENS_PER_E + mblk * BM;
    const float* hg  = g_h + (size_t)tok_base * HIDDEN_DIM;
    const float* w2g = w2  + (size_t)e * HIDDEN_DIM * DIM + nblk * BN;

    float acc[2][4][4];
#pragma unroll
    for (int mt = 0; mt < 2; mt++)
#pragma unroll
        for (int nt = 0; nt < 4; nt++)
#pragma unroll
            for (int i = 0; i < 4; i++) acc[mt][nt][i] = 0.0f;

    const int xr  = tid >> 3;
    const int xc4 = (tid & 7) * 4;
    const int wr  = tid >> 4;
    const int wc4 = (tid & 15) * 4;

    // Prologue
    {
        float4 px[4], pw[2];
        ldg_x4(hg, HIDDEN_DIM, 0, xr, xc4, px);
        ldg_w2(w2g, DIM, 0, wr, wc4, pw);
        sts_x4(Hs, xr, xc4, px);
        sts_w2(Ws, wr, wc4, pw);
    }
    __syncthreads();

    int cur = 0;
#pragma unroll 1
    for (int k0 = 0; k0 < HIDDEN_DIM; k0 += BK) {
        const bool has_next = (k0 + BK) < HIDDEN_DIM;

        float4 px[4], pw[2];
        if (has_next) {
            ldg_x4(hg, HIDDEN_DIM, k0 + BK, xr, xc4, px);
            ldg_w2(w2g, DIM, k0 + BK, wr, wc4, pw);
        }

        const float* Hb = Hs + cur * X_BUF;
        const float* Wb = Ws + cur * W_BUF;

#pragma unroll
        for (int ks = 0; ks < BK; ks += 8) {
            uint32_t a[2][4];
            const int ar = wm * 32 + (lane >> 2);
            const int ac = ks + (lane & 3);
#pragma unroll
            for (int mt = 0; mt < 2; mt++) {
                const int r = ar + mt * 16;
                a[mt][0] = __float_as_uint(Hb[r       * XS_STRIDE + ac]);
                a[mt][1] = __float_as_uint(Hb[(r + 8) * XS_STRIDE + ac]);
                a[mt][2] = __float_as_uint(Hb[r       * XS_STRIDE + ac + 4]);
                a[mt][3] = __float_as_uint(Hb[(r + 8) * XS_STRIDE + ac + 4]);
            }
            const int br = ks + (lane & 3);
#pragma unroll
            for (int nt = 0; nt < 4; nt++) {
                const int bc = wn * 32 + nt * 8 + (lane >> 2);
                const uint32_t b0 = __float_as_uint(Wb[br       * WS_STRIDE + bc]);
                const uint32_t b1 = __float_as_uint(Wb[(br + 4) * WS_STRIDE + bc]);
#pragma unroll
                for (int mt = 0; mt < 2; mt++) {
                    mma_tf32(acc[mt][nt], a[mt], b0, b1);
                }
            }
        }

        if (has_next) {
            const int nxt = cur ^ 1;
            sts_x4(Hs + nxt * X_BUF, xr, xc4, px);
            sts_w2(Ws + nxt * W_BUF, wr, wc4, pw);
        }
        __syncthreads();
        cur ^= 1;
    }

    const int row_base = wm * 32 + (lane >> 2);
    const int col_base = nblk * BN + wn * 32 + (lane & 3) * 2;
#pragma unroll
    for (int mt = 0; mt < 2; mt++) {
        const int r0 = tok_base + row_base + mt * 16;
#pragma unroll
        for (int nt = 0; nt < 4; nt++) {
            const int c = col_base + nt * 8;
            float2 lo = make_float2(acc[mt][nt][0], acc[mt][nt][1]);
            float2 hi = make_float2(acc[mt][nt][2], acc[mt][nt][3]);
            *reinterpret_cast<float2*>(&out[(size_t)r0 * DIM + c])       = lo;
            *reinterpret_cast<float2*>(&out[(size_t)(r0 + 8) * DIM + c]) = hi;
        }
    }
}

// ---- launch ----------------------------------------------------------------

extern "C" void kernel_launch(void* const* d_in, const int* in_sizes, int n_in,
                              void* d_out, int out_size) {
    const float* x  = (const float*)d_in[0];
    const float* w1 = (const float*)d_in[1];
    const float* w2 = (const float*)d_in[2];
    const float* w3 = (const float*)d_in[3];
    // d_in[4] = num_local_tokens_per_expert: statically 256 each, unused.
    float* out = (float*)d_out;

    // Opt-in to >48KB dynamic smem (idempotent; not an allocation, capture-safe).
    cudaFuncSetAttribute(moe_up_kernel,
                         cudaFuncAttributeMaxDynamicSharedMemorySize, SMEM_UP_BYTES);
    cudaFuncSetAttribute(moe_down_kernel,
                         cudaFuncAttributeMaxDynamicSharedMemorySize, SMEM_DOWN_BYTES);

    dim3 blk(256);
    moe_up_kernel<<<dim3(HIDDEN_DIM / BN, TOKENS_PER_E / BM, NUM_EXPERTS), blk,
                    SMEM_UP_BYTES>>>(x, w1, w3);
    moe_down_kernel<<<dim3(DIM / BN, TOKENS_PER_E / BM, NUM_EXPERTS), blk,
                      SMEM_DOWN_BYTES>>>(w2, out);
}

// round 11
// speedup vs baseline: 1.2140x; 1.1204x over previous
#include <cuda_runtime.h>
#include <cstdint>

// ---------------- problem constants ----------------
#define NUM_EXPERTS   64
#define DIM           2048
#define HIDDEN_DIM    1024
#define TOKENS_PER_E  256
#define TOTAL_TOKENS  (NUM_EXPERTS * TOKENS_PER_E)   // 16384

// ---------------- tiling ----------------
// CTA tile 128x128, BK=32. 4 warps in 2x2 grid; warp tile 64x64 (mt=4, nt=8).
#define BM 128
#define BN 128
#define BK 32
#define XS_STRIDE 36    // 32+4 pad: conflict-free for frag LDS and staging STS
#define WS_STRIDE 136   // 128+8 pad: 136 % 32 == 8 -> conflict-free patterns
#define X_BUF (BM * XS_STRIDE)        // 4608 floats
#define W_BUF (BK * WS_STRIDE)        // 4352 floats
#define SMEM_BYTES (2 * (X_BUF + W_BUF) * 4)   // 71680 B (double-buffered)

// Scratch: g1 = x@w1 (gate pre-activation), h = swiglu output. 64 MB each.
__device__ float g_t1[(size_t)TOTAL_TOKENS * HIDDEN_DIM];
__device__ float g_h [(size_t)TOTAL_TOKENS * HIDDEN_DIM];

// ---------------- helpers ----------------

__device__ __forceinline__ float tf32_rna(float f) {
    asm("cvt.rna.tf32.f32 %0, %0;" : "+f"(f));
    return f;
}

__device__ __forceinline__ void mma_tf32(float c[4],
                                         const uint32_t a[4],
                                         uint32_t b0, uint32_t b1) {
    asm volatile(
        "mma.sync.aligned.m16n8k8.row.col.f32.tf32.tf32.f32 "
        "{%0,%1,%2,%3}, {%4,%5,%6,%7}, {%8,%9}, {%0,%1,%2,%3};"
        : "+f"(c[0]), "+f"(c[1]), "+f"(c[2]), "+f"(c[3])
        : "r"(a[0]), "r"(a[1]), "r"(a[2]), "r"(a[3]), "r"(b0), "r"(b1));
}

__device__ __forceinline__ float silu(float g) {
    return g / (1.0f + __expf(-g));
}

// ---------------- staging (128 threads) ----------------
// X tile [128 rows][32 k], rows = sr + 16p (p=0..7), 8 lanes of a warp share a
// row (lane&7 -> 4-float column chunk) -> STS phases hit 8 distinct banks.
// W tile [32 k-rows][128 n], rows = sr + 16p (p=0..1), 4 column blocks.

struct Stage {
    float4 x[8];
    float4 w[8];
};

__device__ __forceinline__ void ldg_stage(Stage& s,
                                          const float* __restrict__ Ag, int lda,
                                          const float* __restrict__ Wg, int ldw,
                                          int k0, int sr, int sc4) {
#pragma unroll
    for (int p = 0; p < 8; p++)
        s.x[p] = *reinterpret_cast<const float4*>(Ag + (size_t)(sr + p * 16) * lda + k0 + sc4);
#pragma unroll
    for (int p = 0; p < 2; p++)
#pragma unroll
        for (int cb = 0; cb < 4; cb++)
            s.w[p * 4 + cb] = *reinterpret_cast<const float4*>(
                Wg + (size_t)(k0 + sr + p * 16) * ldw + cb * 32 + sc4);
}

__device__ __forceinline__ float4 rna4(float4 v) {
    v.x = tf32_rna(v.x); v.y = tf32_rna(v.y); v.z = tf32_rna(v.z); v.w = tf32_rna(v.w);
    return v;
}

__device__ __forceinline__ void sts_stage(const Stage& s,
                                          float* __restrict__ Xd,
                                          float* __restrict__ Wd,
                                          int sr, int sc4) {
#pragma unroll
    for (int p = 0; p < 8; p++)
        *reinterpret_cast<float4*>(&Xd[(sr + p * 16) * XS_STRIDE + sc4]) = rna4(s.x[p]);
#pragma unroll
    for (int p = 0; p < 2; p++)
#pragma unroll
        for (int cb = 0; cb < 4; cb++)
            *reinterpret_cast<float4*>(&Wd[(sr + p * 16) * WS_STRIDE + cb * 32 + sc4]) =
                rna4(s.w[p * 4 + cb]);
}

// ---------------- GEMM template ----------------
// out[row][col] (+ optional swiglu with gate) = A[BMxK] @ W[e][KxN]
// EPI: 0 = plain store, 1 = out = silu(gate) * acc

template<int KTOT, int NTOT, int EPI>
__global__ __launch_bounds__(128, 2)
void gemm_kernel(const float* __restrict__ A,
                 const float* __restrict__ W,
                 const float* __restrict__ gate,
                 float* __restrict__ out) {
    extern __shared__ float sm[];
    float* Xs = sm;               // [2][X_BUF]
    float* Ws = sm + 2 * X_BUF;   // [2][W_BUF]

    const int e    = blockIdx.z;
    const int mblk = blockIdx.y;
    const int nblk = blockIdx.x;
    const int tid  = threadIdx.x;
    const int lane = tid & 31;
    const int warp = tid >> 5;
    const int wm   = warp >> 1;   // 0..1 (M half)
    const int wn   = warp & 1;    // 0..1 (N half)

    const int tok_base = e * TOKENS_PER_E + mblk * BM;
    const float* Ag = A + (size_t)tok_base * KTOT;
    const float* Wg = W + (size_t)e * KTOT * NTOT + nblk * BN;

    float acc[4][8][4];
#pragma unroll
    for (int mt = 0; mt < 4; mt++)
#pragma unroll
        for (int nt = 0; nt < 8; nt++)
#pragma unroll
            for (int i = 0; i < 4; i++) acc[mt][nt][i] = 0.0f;

    const int sr  = tid >> 3;        // 0..15
    const int sc4 = (tid & 7) * 4;   // 0..28

    const int NK = KTOT / BK;

    Stage s;
    ldg_stage(s, Ag, KTOT, Wg, NTOT, 0, sr, sc4);
    sts_stage(s, Xs, Ws, sr, sc4);
    __syncthreads();

#pragma unroll 1
    for (int i = 0; i < NK; i++) {
        const int cur = i & 1;
        const bool has_next = (i + 1) < NK;

        if (has_next)
            ldg_stage(s, Ag, KTOT, Wg, NTOT, (i + 1) * BK, sr, sc4);

        const float* Xb = Xs + cur * X_BUF;
        const float* Wb = Ws + cur * W_BUF;
        const int q = lane >> 2;
        const int j = lane & 3;

#pragma unroll
        for (int ks = 0; ks < BK; ks += 8) {
            uint32_t a[4][4];
            const int ac = ks + j;
#pragma unroll
            for (int mt = 0; mt < 4; mt++) {
                const int r = wm * 64 + mt * 16 + q;
                a[mt][0] = __float_as_uint(Xb[r       * XS_STRIDE + ac]);
                a[mt][1] = __float_as_uint(Xb[(r + 8) * XS_STRIDE + ac]);
                a[mt][2] = __float_as_uint(Xb[r       * XS_STRIDE + ac + 4]);
                a[mt][3] = __float_as_uint(Xb[(r + 8) * XS_STRIDE + ac + 4]);
            }
            const int br = ks + j;
#pragma unroll
            for (int nt = 0; nt < 8; nt++) {
                const int bc = wn * 64 + nt * 8 + q;
                const uint32_t b0 = __float_as_uint(Wb[br       * WS_STRIDE + bc]);
                const uint32_t b1 = __float_as_uint(Wb[(br + 4) * WS_STRIDE + bc]);
#pragma unroll
                for (int mt = 0; mt < 4; mt++)
                    mma_tf32(acc[mt][nt], a[mt], b0, b1);
            }
        }

        if (has_next) {
            const int nxt = cur ^ 1;
            sts_stage(s, Xs + nxt * X_BUF, Ws + nxt * W_BUF, sr, sc4);
        }
        __syncthreads();
    }

    // ---- epilogue ----
    const int q = lane >> 2;
    const int j = lane & 3;
#pragma unroll
    for (int mt = 0; mt < 4; mt++) {
#pragma unroll
        for (int h = 0; h < 2; h++) {
            const int row = tok_base + wm * 64 + mt * 16 + q + h * 8;
#pragma unroll
            for (int nt = 0; nt < 8; nt++) {
                const int col = nblk * BN + wn * 64 + nt * 8 + j * 2;
                float v0 = acc[mt][nt][h * 2 + 0];
                float v1 = acc[mt][nt][h * 2 + 1];
                if (EPI == 1) {
                    float2 g = *reinterpret_cast<const float2*>(
                        gate + (size_t)row * NTOT + col);
                    v0 = silu(g.x) * v0;
                    v1 = silu(g.y) * v1;
                }
                *reinterpret_cast<float2*>(out + (size_t)row * NTOT + col) =
                    make_float2(v0, v1);
            }
        }
    }
}

// ---------------- launch ----------------

extern "C" void kernel_launch(void* const* d_in, const int* in_sizes, int n_in,
                              void* d_out, int out_size) {
    const float* x  = (const float*)d_in[0];
    const float* w1 = (const float*)d_in[1];
    const float* w2 = (const float*)d_in[2];
    const float* w3 = (const float*)d_in[3];
    float* out = (float*)d_out;

    float *t1, *h;
    cudaGetSymbolAddress((void**)&t1, g_t1);   // host-side query, capture-safe
    cudaGetSymbolAddress((void**)&h,  g_h);

    cudaFuncSetAttribute(gemm_kernel<DIM, HIDDEN_DIM, 0>,
                         cudaFuncAttributeMaxDynamicSharedMemorySize, SMEM_BYTES);
    cudaFuncSetAttribute(gemm_kernel<DIM, HIDDEN_DIM, 1>,
                         cudaFuncAttributeMaxDynamicSharedMemorySize, SMEM_BYTES);
    cudaFuncSetAttribute(gemm_kernel<HIDDEN_DIM, DIM, 0>,
                         cudaFuncAttributeMaxDynamicSharedMemorySize, SMEM_BYTES);

    dim3 blk(128);
    dim3 grid_up(HIDDEN_DIM / BN, TOKENS_PER_E / BM, NUM_EXPERTS);   // (8, 2, 64)
    dim3 grid_dn(DIM / BN,        TOKENS_PER_E / BM, NUM_EXPERTS);   // (16, 2, 64)

    // U1: g1 = x @ w1
    gemm_kernel<DIM, HIDDEN_DIM, 0><<<grid_up, blk, SMEM_BYTES>>>(x, w1, nullptr, t1);
    // U2: h = silu(g1) * (x @ w3)
    gemm_kernel<DIM, HIDDEN_DIM, 1><<<grid_up, blk, SMEM_BYTES>>>(x, w3, t1, h);
    // D:  out = h @ w2
    gemm_kernel<HIDDEN_DIM, DIM, 0><<<grid_dn, blk, SMEM_BYTES>>>(h, w2, nullptr, out);
}